// round 14
// baseline (speedup 1.0000x reference)
#include <cuda_runtime.h>
#include <cuda_fp16.h>

// CRF NLL mean — B=256, S=512, T=64.
// Bidirectional split (fwd: transitions 1..255, bwd: 511..256), combined at
// the midpoint. One self-contained warp per chain; block = 2 batches x
// {fwd,bwd}; grid=128 -> 1 block/SM, 1 warp/SMSP. R14: the 64-wide
// contraction runs in fp16 (HFMA2, rt 2 = 2x fp32 MAC rate); published
// vector is power-of-two normalized (exact, tracked in eoff) to keep fp16
// in range; state/emissions/renorm stay fp32.

constexpr int NT  = 64;
constexpr int NB  = 256;
constexpr int NS  = 512;

__device__ float g_llh[NB];
__device__ int   g_cnt = 0;

__device__ __forceinline__ float warp_sum_f(float v) {
#pragma unroll
    for (int o = 16; o > 0; o >>= 1) v += __shfl_down_sync(0xffffffffu, v, o);
    return v;
}
__device__ __forceinline__ int warp_sum_i(int v) {
#pragma unroll
    for (int o = 16; o > 0; o >>= 1) v += __shfl_down_sync(0xffffffffu, v, o);
    return v;
}

// 64-contraction in fp16: pb holds 64 pre-duplicated half2 (u_i,u_i); Ehp[i] =
// (E_i->j0, E_i->j1). 16 broadcast LDS.128 + 64 HFMA2, 8-way ILP.
__device__ __forceinline__ float2 dot_fp16(
    const unsigned int* __restrict__ pb, const __half2* __restrict__ Ehp)
{
    __half2 z = __float2half2_rn(0.0f);
    __half2 a0=z,a1=z,a2=z,a3=z,a4=z,a5=z,a6=z,a7=z;
    const uint4* p4 = (const uint4*)pb;   // 16 x 16B broadcast
#pragma unroll
    for (int g = 0; g < 16; g += 2) {
        uint4 q0 = p4[g];
        uint4 q1 = p4[g + 1];
        a0 = __hfma2(*(const __half2*)&q0.x, Ehp[4*g + 0], a0);
        a1 = __hfma2(*(const __half2*)&q0.y, Ehp[4*g + 1], a1);
        a2 = __hfma2(*(const __half2*)&q0.z, Ehp[4*g + 2], a2);
        a3 = __hfma2(*(const __half2*)&q0.w, Ehp[4*g + 3], a3);
        a4 = __hfma2(*(const __half2*)&q1.x, Ehp[4*g + 4], a4);
        a5 = __hfma2(*(const __half2*)&q1.y, Ehp[4*g + 5], a5);
        a6 = __hfma2(*(const __half2*)&q1.z, Ehp[4*g + 6], a6);
        a7 = __hfma2(*(const __half2*)&q1.w, Ehp[4*g + 7], a7);
    }
    a0 = __hadd2(a0, a1); a2 = __hadd2(a2, a3);
    a4 = __hadd2(a4, a5); a6 = __hadd2(a6, a7);
    a0 = __hadd2(a0, a2); a4 = __hadd2(a4, a6);
    a0 = __hadd2(a0, a4);
    return __half22float2(a0);
}

__global__ __launch_bounds__(128, 1) void crf_forward_kernel(
    const float* __restrict__ em,        // (B,S,T)
    const int*   __restrict__ tags32,    // (B,S) int32 (or int64 viewed as pairs)
    const int*   __restrict__ mask,      // (B,S)
    const float* __restrict__ startT,
    const float* __restrict__ endT,
    const float* __restrict__ trans,
    float*       __restrict__ out)
{
    const int tid = threadIdx.x;
    const int w   = tid >> 5;            // warp 0..3 -> SMSP 0..3
    const int t   = tid & 31;            // lane; owns outputs j0=2t, j1=2t+1
    const int bs  = w >> 1;
    const int dir = w & 1;               // 0 = forward, 1 = backward
    const int b   = blockIdx.x * 2 + bs;

    // per-warp double-buffered published vector: 64 duplicated half2 = 256B
    __shared__ __align__(16) unsigned int ubuf[4][2][NT];
    __shared__ float fv[2][2][NT];
    __shared__ float nsh[4];
    __shared__ int   msh[4], eosh[4];

    bool is64 = true;
#pragma unroll
    for (int k = 0; k < 16; k++) is64 &= (tags32[2 * k + 1] == 0);

    const int j0 = 2 * t, j1 = 2 * t + 1;

    // E in fp16 pairs over the contraction dim (64 regs)
    __half2 Ehp[NT];
    if (dir == 0) {
        // fwd: out j0/j1 = columns; contraction over rows i
#pragma unroll
        for (int i = 0; i < NT; i++) {
            float2 tv = *(const float2*)(trans + i * NT + j0);
            Ehp[i] = __floats2half2_rn(__expf(tv.x), __expf(tv.y));
        }
    } else {
        // bwd: out j0/j1 = rows; contraction over columns i
#pragma unroll
        for (int i = 0; i < NT; i++) {
            float ea = __expf(trans[j0 * NT + i]);
            float eb = __expf(trans[j1 * NT + i]);
            Ehp[i] = __floats2half2_rn(ea, eb);
        }
    }

    const float* emb  = em + (size_t)b * NS * NT;
    const int*   mrow = mask + b * NS;
    unsigned int* myb0 = ubuf[w][0];
    unsigned int* myb1 = ubuf[w][1];

    const int  srow0 = dir ? (NS - 1) : 0;
    const int  sstep = dir ? -1 : 1;
    const float* ep0 = emb + srow0 * NT + j0;
    const long rstride = (long)sstep * NT;

    float ua, ub;                         // fp32 chain state
    int eoff = 0;
    if (dir == 0) {
        float2 st2 = *(const float2*)(startT + j0);
        float2 e0v = *(const float2*)(emb + j0);
        ua = __expf(st2.x + e0v.x);
        ub = __expf(st2.y + e0v.y);
    } else {
        float2 en2 = *(const float2*)(endT + j0);
        ua = __expf(en2.x);
        ub = __expf(en2.y);
    }
    const int isBwd = dir;

    // depth-4 rotating prefetch (always in-bounds)
    float2 ev[4]; int mv[4];
#pragma unroll
    for (int k = 0; k < 4; k++) {
        ev[k] = *(const float2*)(ep0 + (long)k * rstride);
        mv[k] = mrow[srow0 + k * sstep];
    }
    if (dir == 0) mv[0] = 0;              // fwd dummy step

    for (int ko = 0; ko < 64; ko++) {
#pragma unroll
        for (int kk = 0; kk < 4; kk++) {
            const int k  = 4 * ko + kk;
            const int bi = k & 1;
            float ea = __expf(ev[kk].x);
            float eb = __expf(ev[kk].y);
            int   mk = mv[kk];
            float2 ev_n = *(const float2*)(ep0 + (long)(k + 4) * rstride);
            int    mv_n = mrow[srow0 + (k + 4) * sstep];

            // value to publish: fwd = u, bwd = e_s ∘ v
            float pa = isBwd ? (ua * ea) : ua;
            float pbv = isBwd ? (ub * eb) : ub;

            // publish-time exact power-of-two normalization (band ~2^-4)
            float p0 = __shfl_sync(0xffffffffu, pa, 0);
            int   e0 = ((__float_as_int(p0) >> 23) & 0xff) - 127 + 4;
            float sc = __int_as_float((127 - e0) << 23);   // 2^-e0, exact

            __half2 h2 = __floats2half2_rn(pa * sc, pbv * sc);
            unsigned int h = *(unsigned int*)&h2;
            unsigned int haa = __byte_perm(h, h, 0x1010);  // (h.lo, h.lo)
            unsigned int hbb = __byte_perm(h, h, 0x3232);  // (h.hi, h.hi)
            unsigned int* pb = bi ? myb1 : myb0;
            *(uint2*)(pb + j0) = make_uint2(haa, hbb);
            __syncwarp(0xffffffffu);

            float2 o = dot_fp16(pb, Ehp);

            // output: fwd folds emission of step s; bwd does not
            float na = isBwd ? o.x : (o.x * ea);
            float nb = isBwd ? o.y : (o.y * eb);
            const bool keep = (mk != 0);
            ua = keep ? na : ua;
            ub = keep ? nb : ub;
            eoff += e0 & (-mk);
            ev[kk] = ev_n; mv[kk] = mv_n;
        }
    }

    // midpoint vectors (fp32 state)
    fv[bs][dir][j0] = ua;
    fv[bs][dir][j1] = ub;

    // ---- numerator partial over this warp's half of S + mask count ----
    float npart = 0.0f; int mcount = 0;
    const size_t tbase = (size_t)b * NS;
    const int sBeg = dir ? (NS / 2) : 0;
    const int sEnd = sBeg + NS / 2;
    for (int s = sBeg + t; s < sEnd; s += 32) {
        size_t idx = tbase + s;
        int tg = is64 ? tags32[2 * idx] : tags32[idx];
        float emv = emb[s * NT + tg];
        if (s == 0) {
            npart += startT[tg] + emv;
        } else if (mrow[s]) {
            size_t idp = tbase + s - 1;
            int tp = is64 ? tags32[2 * idp] : tags32[idp];
            npart += trans[tp * NT + tg] + emv;
        }
        mcount += (mrow[s] != 0);
    }
    npart  = warp_sum_f(npart);
    mcount = warp_sum_i(mcount);
    if (t == 0) { nsh[w] = npart; msh[w] = mcount; eosh[w] = eoff; }
    __syncthreads();

    // ---- combine: warp 0 -> batch slot 0, warp 2 -> batch slot 1 ----
    if (dir == 0) {
        float z = fv[bs][0][j0] * fv[bs][1][j0]
                + fv[bs][0][j1] * fv[bs][1][j1];
        z = warp_sum_f(z);
        if (t == 0) {
            int   etot = eosh[2 * bs] + eosh[2 * bs + 1];
            int   mc   = msh[2 * bs] + msh[2 * bs + 1];
            float ns   = nsh[2 * bs] + nsh[2 * bs + 1];
            size_t lidx = tbase + (mc - 1);
            int last = is64 ? tags32[2 * lidx] : tags32[lidx];
            ns += endT[last];
            double denom = (double)etot * 0.6931471805599453 + (double)logf(z);
            g_llh[b] = (float)(denom - (double)ns);

            __threadfence();
            int ticket = atomicAdd(&g_cnt, 1);
            if (ticket == NB - 1) {
                float acc = 0.0f;
#pragma unroll 8
                for (int i = 0; i < NB; i++) acc += __ldcg(&g_llh[i]);
                *out = acc / (float)NB;
                g_cnt = 0;                    // self-reset for graph replay
            }
        }
    }
}

extern "C" void kernel_launch(void* const* d_in, const int* in_sizes, int n_in,
                              void* d_out, int out_size)
{
    const float* em   = (const float*)d_in[0];
    const int*   tags = (const int*)d_in[1];
    const int*   mask = (const int*)d_in[2];
    const float* st   = (const float*)d_in[3];
    const float* en   = (const float*)d_in[4];
    const float* tr   = (const float*)d_in[5];

    crf_forward_kernel<<<NB / 2, 128>>>(em, tags, mask, st, en, tr, (float*)d_out);
}